// round 1
// baseline (speedup 1.0000x reference)
#include <cuda_runtime.h>
#include <cstdint>

// out[b,h,w,c] = x[b,h,w,c] + (c < 512 ? spatial_pe[h,w,c]
//                                      : pattern_pe[pattern_indices[b,h,w] % 64][c-512])
// Shapes: x [64,30,30,1024] f32, pattern_indices [64,30,30] i32,
//         spatial_pe [30,30,512] f32, pattern_pe [64,512] f32.
// H == W == MAX_GRID == 30, so spatial_pe[:h,:w] is the full table.

static constexpr int D_MODEL   = 1024;
static constexpr int D4        = D_MODEL / 4;   // 256 float4 per pixel
static constexpr int HALF4     = D4 / 2;        // 128: split point spatial/pattern
static constexpr int NPIX      = 64 * 30 * 30;  // 57600 pixels
static constexpr int HW        = 30 * 30;
static constexpr int NUM_PAT   = 64;
static constexpr long long TOTAL4 = (long long)NPIX * D4; // 14,745,600

__global__ void __launch_bounds__(256)
pe_add_kernel(const float4* __restrict__ x4,
              const int*    __restrict__ pidx,
              const float4* __restrict__ sp4,   // [900, 128] float4
              const float4* __restrict__ pp4,   // [64, 128] float4
              float4*       __restrict__ out4)
{
    long long i = (long long)blockIdx.x * blockDim.x + threadIdx.x;
    if (i >= TOTAL4) return;

    int c4    = (int)(i & (D4 - 1));      // D4=256 is pow2
    int pixel = (int)(i >> 8);            // i / 256

    float4 xv = x4[i];
    float4 pe;
    if (c4 < HALF4) {
        int hw = pixel % HW;              // spatial depends only on (h,w)
        pe = sp4[(long long)hw * HALF4 + c4];
    } else {
        unsigned p = (unsigned)pidx[pixel] % NUM_PAT;
        pe = pp4[(long long)p * HALF4 + (c4 - HALF4)];
    }

    xv.x += pe.x; xv.y += pe.y; xv.z += pe.z; xv.w += pe.w;
    out4[i] = xv;
}

extern "C" void kernel_launch(void* const* d_in, const int* in_sizes, int n_in,
                              void* d_out, int out_size)
{
    const float4* x4   = (const float4*)d_in[0];
    const int*    pidx = (const int*)d_in[1];
    const float4* sp4  = (const float4*)d_in[2];
    const float4* pp4  = (const float4*)d_in[3];
    float4*       out4 = (float4*)d_out;

    const int threads = 256;
    const int blocks  = (int)((TOTAL4 + threads - 1) / threads); // 57600
    pe_add_kernel<<<blocks, threads>>>(x4, pidx, sp4, pp4, out4);
}

// round 2
// speedup vs baseline: 1.1321x; 1.1321x over previous
#include <cuda_runtime.h>
#include <cstdint>

// out[b,h,w,c] = x[b,h,w,c] + (c < 512 ? spatial_pe[h,w,c]
//                                      : pattern_pe[pattern_indices[b,h,w] % 64][c-512])
// x [64,30,30,1024] f32, pattern_indices [64,30,30] i32,
// spatial_pe [30,30,512] f32, pattern_pe [64,512] f32.  H==W==MAX_GRID==30.
//
// Layout: grid = (225, 64). Block (256 thr) covers 4 consecutive pixels of one
// batch image (4 * 256 float4 = 4 KB in, 4 KB out). Thread t handles channel
// chunk c4 = t for all 4 pixels -> 8 independent front-batched 128-bit LDGs
// (4 x, 4 PE) per thread to maximize MLP, then 4 STGs.

static constexpr int D4      = 256;   // float4 per pixel (1024 f32)
static constexpr int HALF4   = 128;   // spatial/pattern split in float4 units
static constexpr int HW      = 900;   // 30*30
static constexpr int PIX_PER_BLK = 4;
static constexpr int NUM_PAT = 64;

__global__ void __launch_bounds__(256)
pe_add_kernel(const float4* __restrict__ x4,
              const int*    __restrict__ pidx,
              const float4* __restrict__ sp4,   // [900, 128] float4
              const float4* __restrict__ pp4,   // [64, 128] float4
              float4*       __restrict__ out4)
{
    const int tid = threadIdx.x;
    const int hw0 = blockIdx.x * PIX_PER_BLK;       // 0..896, step 4
    const int b   = blockIdx.y;
    const int pix0 = b * HW + hw0;                  // multiple of 4 (900 % 4 == 0)

    const long long i0 = (long long)pix0 * D4 + tid;

    // 4 pattern indices in one 16B load (pix0 is 4-aligned).
    const int4 pi = *reinterpret_cast<const int4*>(pidx + pix0);

    // ---- front-batched loads: 4 x + 4 PE, all independent ----
    float4 xv0 = x4[i0 + 0 * D4];
    float4 xv1 = x4[i0 + 1 * D4];
    float4 xv2 = x4[i0 + 2 * D4];
    float4 xv3 = x4[i0 + 3 * D4];

    float4 pe0, pe1, pe2, pe3;
    if (tid < HALF4) {                               // warps 0-3: spatial half
        const float4* s = sp4 + (long long)hw0 * HALF4 + tid;
        pe0 = s[0 * HALF4];
        pe1 = s[1 * HALF4];
        pe2 = s[2 * HALF4];
        pe3 = s[3 * HALF4];
    } else {                                         // warps 4-7: pattern half
        const int c = tid - HALF4;
        pe0 = pp4[(long long)(((unsigned)pi.x) % NUM_PAT) * HALF4 + c];
        pe1 = pp4[(long long)(((unsigned)pi.y) % NUM_PAT) * HALF4 + c];
        pe2 = pp4[(long long)(((unsigned)pi.z) % NUM_PAT) * HALF4 + c];
        pe3 = pp4[(long long)(((unsigned)pi.w) % NUM_PAT) * HALF4 + c];
    }

    xv0.x += pe0.x; xv0.y += pe0.y; xv0.z += pe0.z; xv0.w += pe0.w;
    xv1.x += pe1.x; xv1.y += pe1.y; xv1.z += pe1.z; xv1.w += pe1.w;
    xv2.x += pe2.x; xv2.y += pe2.y; xv2.z += pe2.z; xv2.w += pe2.w;
    xv3.x += pe3.x; xv3.y += pe3.y; xv3.z += pe3.z; xv3.w += pe3.w;

    out4[i0 + 0 * D4] = xv0;
    out4[i0 + 1 * D4] = xv1;
    out4[i0 + 2 * D4] = xv2;
    out4[i0 + 3 * D4] = xv3;
}

extern "C" void kernel_launch(void* const* d_in, const int* in_sizes, int n_in,
                              void* d_out, int out_size)
{
    const float4* x4   = (const float4*)d_in[0];
    const int*    pidx = (const int*)d_in[1];
    const float4* sp4  = (const float4*)d_in[2];
    const float4* pp4  = (const float4*)d_in[3];
    float4*       out4 = (float4*)d_out;

    dim3 grid(HW / PIX_PER_BLK, 64);   // (225, 64)
    pe_add_kernel<<<grid, 256>>>(x4, pidx, sp4, pp4, out4);
}